// round 7
// baseline (speedup 1.0000x reference)
#include <cuda_runtime.h>
#include <cuda_bf16.h>
#include <math.h>

#define Lt   2097153
#define NF   4194304
#define NQ   1048576
#define L1n  1048577
#define L2n  524289
#define L3n  262145
#define NB3C 2049

typedef unsigned long long u64;
typedef unsigned int u32;
typedef __nv_bfloat16 bf16;

__device__ float2 g_A[NF];
__device__ float2 g_B[NF];
__device__ float  g_base[Lt];
__device__ bf16   g_h1hi[33554464], g_h1lo[33554464];
__device__ bf16   g_h2hi[33554496], g_h2lo[33554496];
__device__ __align__(16) bf16 g_w2hi[64*160],  g_w2lo[64*160];
__device__ __align__(16) bf16 g_w3hi[128*320], g_w3lo[128*320];
__device__ float  g_part3[NB3C * 128];
__device__ float  g_progpart[1024];
__device__ float  g_prog_mean;
__device__ float  g_feat[128];
__device__ int    g_ws[40], g_we[40], g_wh[40], g_wk[40];
__device__ float  g_wcoef[40];
__device__ int    g_nw, g_wmax;

#define MMA(d, a, b) \
    asm volatile("mma.sync.aligned.m16n8k16.row.col.f32.bf16.bf16.f32 " \
        "{%0,%1,%2,%3},{%4,%5,%6,%7},{%8,%9},{%0,%1,%2,%3};" \
        : "+f"((d)[0]), "+f"((d)[1]), "+f"((d)[2]), "+f"((d)[3]) \
        : "r"((a)[0]), "r"((a)[1]), "r"((a)[2]), "r"((a)[3]), "r"((b)[0]), "r"((b)[1]))

// ---------------- FFT + spectral ----------------
__global__ void k_prep(const float* __restrict__ z) {
    int i = blockIdx.x * 256 + threadIdx.x;
    g_A[i] = make_float2(i < Lt ? z[i] : 0.0f, 0.0f);
}

__global__ void k_fft4(int srcA, int t2, float sign, float inv_n) {
    const float2* __restrict__ x = srcA ? g_A : g_B;
    float2* __restrict__ y = srcA ? g_B : g_A;
    int idx = blockIdx.x * 256 + threadIdx.x;
    int p = idx >> t2, q = idx & ((1 << t2) - 1), s_ = 1 << t2;
    int i0 = q + (p << t2);
    float2 a = x[i0], b = x[i0 + NQ], c = x[i0 + 2*NQ], d = x[i0 + 3*NQ];
    float ang = sign * 6.2831853071795864f * ((float)p * inv_n);
    float sn, cs; sincosf(ang, &sn, &cs);
    float w2r = cs*cs - sn*sn, w2i = 2.0f*cs*sn;
    float w3r = cs*w2r - sn*w2i, w3i = cs*w2i + sn*w2r;
    float apcx = a.x + c.x, apcy = a.y + c.y, amcx = a.x - c.x, amcy = a.y - c.y;
    float bpdx = b.x + d.x, bpdy = b.y + d.y;
    float sjbx = sign * (d.y - b.y), sjby = sign * (b.x - d.x);
    int o0 = q + ((p << t2) << 2);
    y[o0] = make_float2(apcx + bpdx, apcy + bpdy);
    float v1x = amcx + sjbx, v1y = amcy + sjby;
    y[o0 + s_] = make_float2(v1x*cs - v1y*sn, v1x*sn + v1y*cs);
    float v2x = apcx - bpdx, v2y = apcy - bpdy;
    y[o0 + 2*s_] = make_float2(v2x*w2r - v2y*w2i, v2x*w2i + v2y*w2r);
    float v3x = amcx - sjbx, v3y = amcy - sjby;
    y[o0 + 3*s_] = make_float2(v3x*w3r - v3y*w3i, v3x*w3i + v3y*w3r);
}

__global__ void k_prog(const float* __restrict__ w1, const float* __restrict__ b1,
                       const float* __restrict__ w2, const float* __restrict__ b2,
                       const float* __restrict__ w3, const float* __restrict__ b3,
                       const float* __restrict__ harm) {
    __shared__ float sw1[32], sb1[32], sw2[512], sb2[16], sw3[16], shr[8], sred[256];
    int tid = threadIdx.x;
    if (tid < 32) { sw1[tid] = w1[tid]; sb1[tid] = b1[tid]; }
    if (tid < 16) { sb2[tid] = b2[tid]; sw3[tid] = w3[tid * 8 + 1]; }
    for (int i = tid; i < 512; i += 256) sw2[i] = w2[i];
    if (tid < 8) shr[tid] = harm[tid*4] + harm[tid*4+1] + harm[tid*4+2] + harm[tid*4+3];
    __syncthreads();
    float b3_1 = b3[1], acc = 0.0f;
    for (int t = blockIdx.x * 256 + tid; t < Lt; t += 1024 * 256) {
        float tf = (float)t, tn = tf / 2097153.0f;
        float h1r[32];
        #pragma unroll
        for (int j = 0; j < 32; j++) h1r[j] = fmaxf(tn * sw1[j] + sb1[j], 0.0f);
        float mp1 = b3_1;
        #pragma unroll 4
        for (int k = 0; k < 16; k++) {
            float a2 = sb2[k];
            #pragma unroll
            for (int j = 0; j < 32; j++) a2 += h1r[j] * sw2[j * 16 + k];
            mp1 += fmaxf(a2, 0.0f) * sw3[k];
        }
        float sv = 1.0f + mp1 * sinf((6.2831853071795864f * tf) / 2097153.0f);
        int idx = ((int)floorf((tf / 2097153.0f) * 8.0f)) % 8;
        acc += sv * shr[idx];
    }
    sred[tid] = acc; __syncthreads();
    for (int s = 128; s > 0; s >>= 1) { if (tid < s) sred[tid] += sred[tid + s]; __syncthreads(); }
    if (tid == 0) g_progpart[blockIdx.x] = sred[0];
}

__global__ void k_progfinal() {
    __shared__ double sd[256];
    int tid = threadIdx.x; double a = 0.0;
    for (int i = tid; i < 1024; i += 256) a += (double)g_progpart[i];
    sd[tid] = a; __syncthreads();
    for (int s = 128; s > 0; s >>= 1) { if (tid < s) sd[tid] += sd[tid + s]; __syncthreads(); }
    if (tid == 0) g_prog_mean = (float)(sd[0] / (4.0 * 2097153.0));
}

__global__ void k_wininit() {
    const double SPECd[8] = {7.83, 528.0, 396.0, 2.5, 14.1, 432.0, 6.0, 30.0};
    const double val = 1.0 / (4194304.0 * (1.0 / 22050.0));
    int n = 0, wmax = 0;
    for (int k = 0; k < 8; k++)
        for (int m = 1; m <= 5; m++) {
            double hf = SPECd[k] * m;
            if (hf >= 11025.0) continue;
            int i0 = (int)floor(hf / val + 0.5);
            int best = -1; double bd = 1e300;
            for (int i = i0 - 2; i <= i0 + 2; i++) {
                if (i < 0) continue;
                float fr = (float)((double)i * val);
                double d = fabs((double)fr - hf);
                if (d < bd) { bd = d; best = i; }
            }
            int s = best - 15; if (s < 0) s = 0;
            int e = best + 15; if (e > Lt - 1) e = Lt - 1;
            g_ws[n] = s; g_we[n] = e; g_wh[n] = best; g_wk[n] = k;
            g_wcoef[n] = (float)(1.0 / pow((double)m, 1.2));
            if (e > wmax) wmax = e;
            n++;
        }
    g_nw = n; g_wmax = wmax;
}

__global__ void k_passA(const float* __restrict__ band_w, const float* __restrict__ freq_w) {
    int k = blockIdx.x * 256 + threadIdx.x;
    if (k >= Lt) return;
    float kf = (float)k;
    float f = (float)((double)k * (1.0 / (4194304.0 * (1.0 / 22050.0))));
    float M = 1.0f;
    const float lo[6] = {1.f, 4.f, 8.f, 13.f, 30.f, 100.f};
    const float hi[6] = {4.f, 8.f, 13.f, 30.f, 100.f, 200.f};
    if (f <= 200.0f) {
        #pragma unroll
        for (int b = 0; b < 6; b++)
            if (f >= lo[b] && f <= hi[b]) {
                float c = (lo[b] + hi[b]) * 0.5f, hw = (hi[b] - lo[b]) * 0.25f;
                float d = (f - c) / hw;
                float mask = expf(-0.5f * d * d);
                float ab = (float)(6.283185307179586 * (double)c);
                float tmod = sinf((ab * kf) / 22050.0f);
                M = M * (1.0f + mask * band_w[b] * (1.0f + 0.2f * tmod));
            }
    }
    if (k <= g_wmax) {
        float pm1 = 1.0f + g_prog_mean;
        int nw = g_nw;
        for (int w = 0; w < nw; w++)
            if (k >= g_ws[w] && k <= g_we[w]) {
                double dd = (double)(k - g_wh[w]) / 5.0;
                float win = (float)exp(-0.5 * dd * dd);
                M *= (1.0f + freq_w[g_wk[w]] * win * g_wcoef[w] * pm1);
            }
    }
    float2 v = g_B[k];
    g_A[k] = make_float2(v.x * M, v.y * M);
}

__global__ void k_passB() {
    int k = blockIdx.x * 256 + threadIdx.x;
    if (k >= Lt) return;
    float2 xc = g_A[k];
    float m = sqrtf(xc.x * xc.x + xc.y * xc.y);
    float ms;
    if (k == 0 || k == Lt - 1) ms = m;
    else {
        float2 l = g_A[k - 1], r = g_A[k + 1];
        ms = 0.7f * m + 0.15f * sqrtf(l.x*l.x + l.y*l.y) + 0.15f * sqrtf(r.x*r.x + r.y*r.y);
    }
    float2 o;
    if (m > 0.0f) { float sc = ms / m; o = make_float2(xc.x * sc, xc.y * sc); }
    else o = make_float2(ms, 0.0f);
    g_B[k] = o;
    if (k > 0 && k < Lt - 1) g_B[NF - k] = make_float2(o.x, -o.y);
}

__global__ void k_extract() {
    int i = blockIdx.x * 256 + threadIdx.x;
    if (i < Lt) g_base[i] = g_A[i].x * (1.0f / (float)NF);
}

__global__ void k_conv1(const float* __restrict__ w, const float* __restrict__ b) {
    __shared__ float si[520], sw[160], sb[32];
    int tid = threadIdx.x, o0 = blockIdx.x * 256;
    int j0 = 2 * o0 - 2;
    for (int i = tid; i < 516; i += 256) {
        int j = j0 + i;
        si[i] = (j >= 0 && j < Lt) ? g_base[j] : 0.0f;
    }
    if (tid < 160) sw[tid] = w[tid];
    if (tid < 32) sb[tid] = b[tid];
    __syncthreads();
    int o = o0 + tid;
    if (o >= L1n) return;
    float x0 = si[2*tid], x1 = si[2*tid+1], x2 = si[2*tid+2], x3 = si[2*tid+3], x4 = si[2*tid+4];
    #pragma unroll
    for (int c = 0; c < 32; c++) {
        float a = sb[c] + sw[c*5]*x0 + sw[c*5+1]*x1 + sw[c*5+2]*x2 + sw[c*5+3]*x3 + sw[c*5+4]*x4;
        a = a > 0.0f ? a : 0.2f * a;
        bf16 h = __float2bfloat16(a);
        g_h1hi[(size_t)c * L1n + o] = h;
        g_h1lo[(size_t)c * L1n + o] = __float2bfloat16(a - __bfloat162float(h));
    }
}

// weight hi/lo planes — write device globals INSIDE the kernel (no host symbol passing)
template<int CID>
__global__ void k_wprep(const float* __restrict__ w, int n) {
    bf16* ph = (CID == 2) ? g_w2hi : g_w3hi;
    bf16* pl = (CID == 2) ? g_w2lo : g_w3lo;
    int i = blockIdx.x * 256 + threadIdx.x;
    if (i >= n) return;
    float v = w[i];
    bf16 h = __float2bfloat16(v);
    ph[i] = h;
    pl[i] = __float2bfloat16(v - __bfloat162float(h));
}

// conv-as-GEMM on HMMA, direct-LDS fragments. Block: 128 pos x 64 oc, 8 warps (4M x 2N).
// All big buffers are device globals referenced inside (CID selects); bias is a harness ptr.
template<int CID, int IC, int LIN, int LOUT, int NCHUNK, bool FINAL>
__global__ void __launch_bounds__(256, 2) k_convmma(const float* __restrict__ bias)
{
    const bf16* __restrict__ xhi = (CID == 2) ? g_h1hi : g_h2hi;
    const bf16* __restrict__ xlo = (CID == 2) ? g_h1lo : g_h2lo;
    const bf16* __restrict__ whi = (CID == 2) ? g_w2hi : g_w3hi;
    const bf16* __restrict__ wlo = (CID == 2) ? g_w2lo : g_w3lo;
    const int KTOT = IC * 5;
    extern __shared__ char smem[];
    // bytes: A_hi[128][88] @0 (22528), A_lo @22528, B_hi[64][88] @45056 (11264), B_lo @56320, bias @67584
    float* sbias = (float*)(smem + 67584);
    float* sme   = (float*)smem;            // epilogue overlay [64][132]
    float* sredp = (float*)(smem + 34048);  // FINAL: [64][4]
    int tid = threadIdx.x, lane = tid & 31, wid = tid >> 5;
    int wm = wid & 3, wn = wid >> 2;
    int by = blockIdx.y, o0 = blockIdx.x * 128, wbase = by * 64;
    if (tid < 64) sbias[tid] = bias[wbase + tid];

    float acc[2][4][4] = {};
    int mrow = lane >> 2, kcol = 2 * (lane & 3);

    for (int c = 0; c < NCHUNK; c++) {
        __syncthreads();
        // A im2col fill: 128 m x 40 kk-pairs (hi & lo planes)
        #pragma unroll 1
        for (int it = 0; it < 20; it++) {
            int idx = it * 256 + tid;
            int m = idx & 127, kkp = idx >> 7;
            u32 hv = 0, lv = 0;
            #pragma unroll
            for (int s = 0; s < 2; s++) {
                int kk = 2 * kkp + s;
                int ic = c * 16 + kk / 5, k = kk - (kk / 5) * 5;
                int j = 2 * (o0 + m) + k - 2;
                if (j >= 0 && j < LIN) {
                    size_t gi = (size_t)ic * LIN + j;
                    hv |= (u32)*(const unsigned short*)&xhi[gi] << (16 * s);
                    lv |= (u32)*(const unsigned short*)&xlo[gi] << (16 * s);
                }
            }
            int boff = (m * 88 + 2 * kkp) * 2;
            *(u32*)(smem + boff) = hv;
            *(u32*)(smem + 22528 + boff) = lv;
        }
        // B fill: 64 oc x 40 kk-pairs
        #pragma unroll 1
        for (int it = 0; it < 10; it++) {
            int idx = it * 256 + tid;
            int oc = idx / 40, kkp = idx - oc * 40;
            size_t gs = (size_t)(wbase + oc) * KTOT + c * 80 + 2 * kkp;
            int boff = (oc * 88 + 2 * kkp) * 2;
            *(u32*)(smem + 45056 + boff) = *(const u32*)(whi + gs);
            *(u32*)(smem + 56320 + boff) = *(const u32*)(wlo + gs);
        }
        __syncthreads();
        #pragma unroll
        for (int ks = 0; ks < 5; ks++) {
            int k0 = ks * 16;
            // A frags, documented m16n8k16 coords: a0 (m=t/4,k=2(t%4)), a1 m+8, a2 k+8, a3 both
            u32 afr[2][2][4];
            #pragma unroll
            for (int mt = 0; mt < 2; mt++) {
                int e0 = (wm * 32 + mt * 16 + mrow) * 88 + k0 + kcol;
                #pragma unroll
                for (int pl = 0; pl < 2; pl++) {
                    const char* base = smem + pl * 22528;
                    afr[pl][mt][0] = *(const u32*)(base + (size_t)e0 * 2);
                    afr[pl][mt][1] = *(const u32*)(base + (size_t)(e0 + 8 * 88) * 2);
                    afr[pl][mt][2] = *(const u32*)(base + (size_t)(e0 + 8) * 2);
                    afr[pl][mt][3] = *(const u32*)(base + (size_t)(e0 + 8 * 88 + 8) * 2);
                }
            }
            // B frags: b0 (k=2(t%4), n=t/4), b1 k+8 (smem tile is [n][k])
            u32 bfr[2][4][2];
            #pragma unroll
            for (int nt = 0; nt < 4; nt++) {
                int e0 = (wn * 32 + nt * 8 + mrow) * 88 + k0 + kcol;
                #pragma unroll
                for (int pl = 0; pl < 2; pl++) {
                    const char* base = smem + 45056 + pl * 11264;
                    bfr[pl][nt][0] = *(const u32*)(base + (size_t)e0 * 2);
                    bfr[pl][nt][1] = *(const u32*)(base + (size_t)(e0 + 8) * 2);
                }
            }
            #pragma unroll
            for (int mt = 0; mt < 2; mt++)
                #pragma unroll
                for (int nt = 0; nt < 4; nt++) {
                    MMA(acc[mt][nt], afr[0][mt], bfr[0][nt]);
                    MMA(acc[mt][nt], afr[0][mt], bfr[1][nt]);
                    MMA(acc[mt][nt], afr[1][mt], bfr[0][nt]);
                }
        }
    }
    __syncthreads();
    // C frag coords: c0/c1 (m=t/4, n=2(t%4)+{0,1}), c2/c3 m+8
    #pragma unroll
    for (int mt = 0; mt < 2; mt++)
        #pragma unroll
        for (int nt = 0; nt < 4; nt++)
            #pragma unroll
            for (int j = 0; j < 4; j++) {
                int oc = wn * 32 + nt * 8 + kcol + (j & 1);
                int m  = wm * 32 + mt * 16 + mrow + (j >> 1) * 8;
                sme[oc * 132 + m] = acc[mt][nt][j];
            }
    __syncthreads();
    if (FINAL) {
        #pragma unroll 1
        for (int i = 0; i < 32; i++) {
            int idx = i * 256 + tid;
            int oc = idx >> 7, o = idx & 127;
            float v = 0.0f;
            if (o0 + o < LOUT) {
                v = sme[oc * 132 + o] + sbias[oc];
                v = v > 0.0f ? v : 0.2f * v;
            }
            #pragma unroll
            for (int off = 16; off > 0; off >>= 1) v += __shfl_xor_sync(0xffffffffu, v, off);
            if (lane == 0) sredp[oc * 4 + (wid & 3)] = v;
        }
        __syncthreads();
        if (tid < 64)
            g_part3[(size_t)blockIdx.x * 128 + by * 64 + tid] =
                sredp[tid*4] + sredp[tid*4+1] + sredp[tid*4+2] + sredp[tid*4+3];
    } else {
        #pragma unroll 1
        for (int i = 0; i < 32; i++) {
            int idx = i * 256 + tid;
            int oc = idx >> 7, o = idx & 127;
            if (o0 + o < LOUT) {
                float v = sme[oc * 132 + o] + sbias[oc];
                v = v > 0.0f ? v : 0.2f * v;
                bf16 h = __float2bfloat16(v);
                size_t gi = (size_t)oc * LOUT + o0 + o;
                g_h2hi[gi] = h;
                g_h2lo[gi] = __float2bfloat16(v - __bfloat162float(h));
            }
        }
    }
}

__global__ void k_feat() {
    int c = blockIdx.x, tid = threadIdx.x;
    __shared__ double sd[256];
    double a = 0.0;
    for (int bi = tid; bi < NB3C; bi += 256) a += (double)g_part3[(size_t)bi * 128 + c];
    sd[tid] = a; __syncthreads();
    for (int s = 128; s > 0; s >>= 1) { if (tid < s) sd[tid] += sd[tid + s]; __syncthreads(); }
    if (tid == 0) g_feat[c] = (float)(sd[0] / (double)L3n);
}

__global__ void k_mlp(const float* __restrict__ w1, const float* __restrict__ b1,
                      const float* __restrict__ w2, const float* __restrict__ b2,
                      float* __restrict__ out) {
    __shared__ float sf[128], sred[256];
    int tid = threadIdx.x;
    if (tid < 128) sf[tid] = g_feat[tid];
    __syncthreads();
    float acc = b1[tid];
    for (int i = 0; i < 128; i++) acc += sf[i] * w1[i * 256 + tid];
    acc = acc > 0.0f ? acc : 0.2f * acc;
    sred[tid] = acc * w2[tid];
    __syncthreads();
    for (int s = 128; s > 0; s >>= 1) { if (tid < s) sred[tid] += sred[tid + s]; __syncthreads(); }
    if (tid == 0) out[0] = sred[0] + b2[0];
}

#define CONV_SMEM 67840

extern "C" void kernel_launch(void* const* d_in, const int* in_sizes, int n_in,
                              void* d_out, int out_size) {
    (void)in_sizes; (void)n_in; (void)out_size;
    const float* z   = (const float*)d_in[0];
    const float* bw  = (const float*)d_in[2];
    const float* fw  = (const float*)d_in[3];
    const float* hp  = (const float*)d_in[4];
    const float* tw1 = (const float*)d_in[5];  const float* tb1 = (const float*)d_in[6];
    const float* tw2 = (const float*)d_in[7];  const float* tb2 = (const float*)d_in[8];
    const float* tw3 = (const float*)d_in[9];  const float* tb3 = (const float*)d_in[10];
    const float* c1w = (const float*)d_in[11]; const float* c1b = (const float*)d_in[12];
    const float* c2w = (const float*)d_in[13]; const float* c2b = (const float*)d_in[14];
    const float* c3w = (const float*)d_in[15]; const float* c3b = (const float*)d_in[16];
    const float* mw1 = (const float*)d_in[17]; const float* mb1 = (const float*)d_in[18];
    const float* mw2 = (const float*)d_in[19]; const float* mb2 = (const float*)d_in[20];
    float* out = (float*)d_out;

    auto cm2 = k_convmma<2, 32, L1n, L2n, 2, false>;
    auto cm3 = k_convmma<3, 64, L2n, L3n, 4, true>;
    cudaFuncSetAttribute(cm2, cudaFuncAttributeMaxDynamicSharedMemorySize, CONV_SMEM);
    cudaFuncSetAttribute(cm3, cudaFuncAttributeMaxDynamicSharedMemorySize, CONV_SMEM);

    k_prep<<<NF / 256, 256>>>(z);
    int src = 1;
    for (int t = 0; t < 11; t++) { k_fft4<<<NQ/256, 256>>>(src, 2*t, -1.0f, 1.0f/(float)(NF >> (2*t))); src ^= 1; }
    k_prog<<<1024, 256>>>(tw1, tb1, tw2, tb2, tw3, tb3, hp);
    k_progfinal<<<1, 256>>>();
    k_wininit<<<1, 1>>>();
    k_wprep<2><<<(64*160 + 255) / 256, 256>>>(c2w, 64*160);
    k_wprep<3><<<(128*320 + 255) / 256, 256>>>(c3w, 128*320);
    k_passA<<<(Lt + 255) / 256, 256>>>(bw, fw);
    k_passB<<<(Lt + 255) / 256, 256>>>();
    src = 0;
    for (int t = 0; t < 11; t++) { k_fft4<<<NQ/256, 256>>>(src, 2*t, +1.0f, 1.0f/(float)(NF >> (2*t))); src ^= 1; }
    k_extract<<<(Lt + 255) / 256, 256>>>();
    k_conv1<<<(L1n + 255) / 256, 256>>>(c1w, c1b);
    cm2<<<dim3(4097, 1), 256, CONV_SMEM>>>(c2b);
    cm3<<<dim3(2049, 2), 256, CONV_SMEM>>>(c3b);
    k_feat<<<128, 256>>>();
    k_mlp<<<1, 256>>>(mw1, mb1, mw2, mb2, out);
}

// round 8
// speedup vs baseline: 1.2203x; 1.2203x over previous
#include <cuda_runtime.h>
#include <math.h>

#define Lt   2097153
#define N2   2097152
#define NQ2  524288
#define L1n  1048577
#define L2n  524289
#define L3n  262145
#define NB3C 1025

__device__ float2 g_A[N2 + 4];
__device__ float2 g_B[N2 + 4];
__device__ float  g_base[Lt];
__device__ float  g_h1[33554464];
__device__ float  g_h2[33554496];
__device__ float  g_part3[NB3C * 128];
__device__ float  g_progpart[1024];
__device__ float  g_prog_mean;
__device__ float  g_feat[128];
__device__ int    g_ws[40], g_we[40], g_wh[40], g_wk[40];
__device__ float  g_wcoef[40];
__device__ int    g_nw, g_wmax;

// pack real signal (zero-padded to 2^22) as 2^21 complex: z[n] = x[2n] + i x[2n+1]
__global__ void k_prep2(const float* __restrict__ z) {
    int i = blockIdx.x * 256 + threadIdx.x;     // < N2
    int j0 = 2 * i;
    float re = (j0 < Lt)     ? z[j0]     : 0.0f;
    float im = (j0 + 1 < Lt) ? z[j0 + 1] : 0.0f;
    g_A[i] = make_float2(re, im);
}

// Stockham radix-4 stage on N2 points. s = 2^t2. inv_n = 1/(N2>>t2) (exact pow2).
__global__ void k_fft4(int srcA, int t2, float sign, float inv_n) {
    const float2* __restrict__ x = srcA ? g_A : g_B;
    float2* __restrict__ y = srcA ? g_B : g_A;
    int idx = blockIdx.x * 256 + threadIdx.x;   // < NQ2
    int p = idx >> t2, q = idx & ((1 << t2) - 1), s_ = 1 << t2;
    int i0 = q + (p << t2);
    float2 a = x[i0], b = x[i0 + NQ2], c = x[i0 + 2*NQ2], d = x[i0 + 3*NQ2];
    float ang = sign * 6.2831853071795864f * ((float)p * inv_n);
    float sn, cs; sincosf(ang, &sn, &cs);
    float w2r = cs*cs - sn*sn, w2i = 2.0f*cs*sn;
    float w3r = cs*w2r - sn*w2i, w3i = cs*w2i + sn*w2r;
    float apcx = a.x + c.x, apcy = a.y + c.y, amcx = a.x - c.x, amcy = a.y - c.y;
    float bpdx = b.x + d.x, bpdy = b.y + d.y;
    float sjbx = sign * (d.y - b.y), sjby = sign * (b.x - d.x);
    int o0 = q + ((p << t2) << 2);
    y[o0] = make_float2(apcx + bpdx, apcy + bpdy);
    float v1x = amcx + sjbx, v1y = amcy + sjby;
    y[o0 + s_] = make_float2(v1x*cs - v1y*sn, v1x*sn + v1y*cs);
    float v2x = apcx - bpdx, v2y = apcy - bpdy;
    y[o0 + 2*s_] = make_float2(v2x*w2r - v2y*w2i, v2x*w2i + v2y*w2r);
    float v3x = amcx - sjbx, v3y = amcy - sjby;
    y[o0 + 3*s_] = make_float2(v3x*w3r - v3y*w3i, v3x*w3i + v3y*w3r);
}

// final radix-2 stage (s = 2^20, p = 0 -> twiddle = 1)
__global__ void k_fft2(int srcA) {
    const float2* __restrict__ x = srcA ? g_A : g_B;
    float2* __restrict__ y = srcA ? g_B : g_A;
    int q = blockIdx.x * 256 + threadIdx.x;     // < 2^20
    float2 a = x[q], b = x[q + 1048576];
    y[q] = make_float2(a.x + b.x, a.y + b.y);
    y[q + 1048576] = make_float2(a.x - b.x, a.y - b.y);
}

__global__ void k_prog(const float* __restrict__ w1, const float* __restrict__ b1,
                       const float* __restrict__ w2, const float* __restrict__ b2,
                       const float* __restrict__ w3, const float* __restrict__ b3,
                       const float* __restrict__ harm) {
    __shared__ float sw1[32], sb1[32], sw2[512], sb2[16], sw3[16], shr[8], sred[256];
    int tid = threadIdx.x;
    if (tid < 32) { sw1[tid] = w1[tid]; sb1[tid] = b1[tid]; }
    if (tid < 16) { sb2[tid] = b2[tid]; sw3[tid] = w3[tid * 8 + 1]; }
    for (int i = tid; i < 512; i += 256) sw2[i] = w2[i];
    if (tid < 8) shr[tid] = harm[tid*4] + harm[tid*4+1] + harm[tid*4+2] + harm[tid*4+3];
    __syncthreads();
    float b3_1 = b3[1], acc = 0.0f;
    for (int t = blockIdx.x * 256 + tid; t < Lt; t += 1024 * 256) {
        float tf = (float)t, tn = tf / 2097153.0f;
        float h1r[32];
        #pragma unroll
        for (int j = 0; j < 32; j++) h1r[j] = fmaxf(tn * sw1[j] + sb1[j], 0.0f);
        float mp1 = b3_1;
        #pragma unroll 4
        for (int k = 0; k < 16; k++) {
            float a2 = sb2[k];
            #pragma unroll
            for (int j = 0; j < 32; j++) a2 += h1r[j] * sw2[j * 16 + k];
            mp1 += fmaxf(a2, 0.0f) * sw3[k];
        }
        float sv = 1.0f + mp1 * sinf((6.2831853071795864f * tf) / 2097153.0f);
        int idx = ((int)floorf((tf / 2097153.0f) * 8.0f)) % 8;
        acc += sv * shr[idx];
    }
    sred[tid] = acc; __syncthreads();
    for (int s = 128; s > 0; s >>= 1) { if (tid < s) sred[tid] += sred[tid + s]; __syncthreads(); }
    if (tid == 0) g_progpart[blockIdx.x] = sred[0];
}

__global__ void k_progfinal() {
    __shared__ double sd[256];
    int tid = threadIdx.x; double a = 0.0;
    for (int i = tid; i < 1024; i += 256) a += (double)g_progpart[i];
    sd[tid] = a; __syncthreads();
    for (int s = 128; s > 0; s >>= 1) { if (tid < s) sd[tid] += sd[tid + s]; __syncthreads(); }
    if (tid == 0) g_prog_mean = (float)(sd[0] / (4.0 * 2097153.0));
}

__global__ void k_wininit() {
    const double SPECd[8] = {7.83, 528.0, 396.0, 2.5, 14.1, 432.0, 6.0, 30.0};
    const double val = 1.0 / (4194304.0 * (1.0 / 22050.0));
    int n = 0, wmax = 0;
    for (int k = 0; k < 8; k++)
        for (int m = 1; m <= 5; m++) {
            double hf = SPECd[k] * m;
            if (hf >= 11025.0) continue;
            int i0 = (int)floor(hf / val + 0.5);
            int best = -1; double bd = 1e300;
            for (int i = i0 - 2; i <= i0 + 2; i++) {
                if (i < 0) continue;
                float fr = (float)((double)i * val);
                double d = fabs((double)fr - hf);
                if (d < bd) { bd = d; best = i; }
            }
            int s = best - 15; if (s < 0) s = 0;
            int e = best + 15; if (e > Lt - 1) e = Lt - 1;
            g_ws[n] = s; g_we[n] = e; g_wh[n] = best; g_wk[n] = k;
            g_wcoef[n] = (float)(1.0 / pow((double)m, 1.2));
            if (e > wmax) wmax = e;
            n++;
        }
    g_nw = n; g_wmax = wmax;
}

// untangle real-FFT (Z in g_B) -> X[k], multiply by spectral mult -> g_A[k], k<Lt
__global__ void k_passA(const float* __restrict__ band_w, const float* __restrict__ freq_w) {
    int k = blockIdx.x * 256 + threadIdx.x;
    if (k >= Lt) return;
    float2 Zk = g_B[k & (N2 - 1)];
    float2 Zc = g_B[(N2 - k) & (N2 - 1)];
    Zc.y = -Zc.y;
    float Xex = 0.5f * (Zk.x + Zc.x), Xey = 0.5f * (Zk.y + Zc.y);
    float Dx = Zk.x - Zc.x, Dy = Zk.y - Zc.y;
    float Xox = 0.5f * Dy, Xoy = -0.5f * Dx;
    float ang = -6.2831853071795864f * ((float)k * (1.0f / 4194304.0f));
    float sn, cs; sincosf(ang, &sn, &cs);
    float Xr = Xex + cs * Xox - sn * Xoy;
    float Xi = Xey + cs * Xoy + sn * Xox;

    float kf = (float)k;
    float f = (float)((double)k * (1.0 / (4194304.0 * (1.0 / 22050.0))));
    float M = 1.0f;
    const float lo[6] = {1.f, 4.f, 8.f, 13.f, 30.f, 100.f};
    const float hi[6] = {4.f, 8.f, 13.f, 30.f, 100.f, 200.f};
    if (f <= 200.0f) {
        #pragma unroll
        for (int b = 0; b < 6; b++)
            if (f >= lo[b] && f <= hi[b]) {
                float c = (lo[b] + hi[b]) * 0.5f, hw = (hi[b] - lo[b]) * 0.25f;
                float d = (f - c) / hw;
                float mask = expf(-0.5f * d * d);
                float ab = (float)(6.283185307179586 * (double)c);
                float tmod = sinf((ab * kf) / 22050.0f);
                M = M * (1.0f + mask * band_w[b] * (1.0f + 0.2f * tmod));
            }
    }
    if (k <= g_wmax) {
        float pm1 = 1.0f + g_prog_mean;
        int nw = g_nw;
        for (int w = 0; w < nw; w++)
            if (k >= g_ws[w] && k <= g_we[w]) {
                double dd = (double)(k - g_wh[w]) / 5.0;
                float win = (float)exp(-0.5 * dd * dd);
                M *= (1.0f + freq_w[g_wk[w]] * win * g_wcoef[w] * pm1);
            }
    }
    g_A[k] = make_float2(Xr * M, Xi * M);
}

__device__ __forceinline__ float2 smooth_at(int j) {
    float2 xc = g_A[j];
    float m = sqrtf(xc.x * xc.x + xc.y * xc.y);
    float ms;
    if (j == 0 || j == Lt - 1) ms = m;
    else {
        float2 l = g_A[j - 1], r = g_A[j + 1];
        ms = 0.7f * m + 0.15f * sqrtf(l.x*l.x + l.y*l.y) + 0.15f * sqrtf(r.x*r.x + r.y*r.y);
    }
    if (m > 0.0f) { float sc = ms / m; return make_float2(xc.x * sc, xc.y * sc); }
    return make_float2(ms, 0.0f);
}

// smooth + retangle: build Z'[k] for inverse N2-point complex FFT -> g_B
__global__ void k_passB() {
    int k = blockIdx.x * 256 + threadIdx.x;     // < N2
    float2 X1 = smooth_at(k);
    float2 X2 = smooth_at(N2 - k);
    X2.y = -X2.y;  // conj
    float Xex = 0.5f * (X1.x + X2.x), Xey = 0.5f * (X1.y + X2.y);
    float Dx = 0.5f * (X1.x - X2.x), Dy = 0.5f * (X1.y - X2.y);
    float ang = 6.2831853071795864f * ((float)k * (1.0f / 4194304.0f));
    float sn, cs; sincosf(ang, &sn, &cs);
    float Xox = cs * Dx - sn * Dy;
    float Xoy = cs * Dy + sn * Dx;
    g_B[k] = make_float2(Xex - Xoy, Xey + Xox);
}

__global__ void k_extract() {
    int i = blockIdx.x * 256 + threadIdx.x;
    if (i >= Lt) return;
    float2 v = g_A[i >> 1];
    g_base[i] = ((i & 1) ? v.y : v.x) * (1.0f / 2097152.0f);
}

__global__ void k_conv1(const float* __restrict__ w, const float* __restrict__ b) {
    __shared__ float si[520], sw[160], sb[32];
    int tid = threadIdx.x, o0 = blockIdx.x * 256;
    int j0 = 2 * o0 - 2;
    for (int i = tid; i < 516; i += 256) {
        int j = j0 + i;
        si[i] = (j >= 0 && j < Lt) ? g_base[j] : 0.0f;
    }
    if (tid < 160) sw[tid] = w[tid];
    if (tid < 32) sb[tid] = b[tid];
    __syncthreads();
    int o = o0 + tid;
    if (o >= L1n) return;
    float x0 = si[2*tid], x1 = si[2*tid+1], x2 = si[2*tid+2], x3 = si[2*tid+3], x4 = si[2*tid+4];
    #pragma unroll
    for (int c = 0; c < 32; c++) {
        float a = sb[c] + sw[c*5]*x0 + sw[c*5+1]*x1 + sw[c*5+2]*x2 + sw[c*5+3]*x3 + sw[c*5+4]*x4;
        g_h1[(size_t)c * L1n + o] = a > 0.0f ? a : 0.2f * a;
    }
}

// conv2: 32->64, k=5, s=2. 512 threads, 256 positions, all 64 oc. Thread: 4oc x 8pos.
__global__ void __launch_bounds__(512, 1) k_conv2(const float* __restrict__ w, const float* __restrict__ b) {
    extern __shared__ float sm[];
    float* sw = sm;             // [64][165]
    float* si = sm + 64 * 165;  // [32][520]
    int tid = threadIdx.x;
    for (int i = tid; i < 64 * 160; i += 512) { int oc = i / 160, r = i - oc * 160; sw[oc * 165 + r] = w[i]; }
    int o0 = blockIdx.x * 256, j0 = 2 * o0 - 2;
    for (int ii = tid; ii < 32 * 516; ii += 512) {
        int ic = ii / 516, jj = ii - ic * 516, j = j0 + jj;
        si[ic * 520 + jj] = (j >= 0 && j < L1n) ? g_h1[(size_t)ic * L1n + j] : 0.0f;
    }
    __syncthreads();
    int pg = tid & 31, c0 = (tid >> 5) * 4;
    float acc[4][8];
    #pragma unroll
    for (int cc = 0; cc < 4; cc++) { float bb = b[c0 + cc];
        #pragma unroll
        for (int pp = 0; pp < 8; pp++) acc[cc][pp] = bb; }
    for (int ic = 0; ic < 32; ic++)
        #pragma unroll
        for (int k = 0; k < 5; k++) {
            float wr[4];
            #pragma unroll
            for (int cc = 0; cc < 4; cc++) wr[cc] = sw[(c0 + cc) * 165 + ic * 5 + k];
            #pragma unroll
            for (int pp = 0; pp < 8; pp++) {
                float iv = si[ic * 520 + 2 * pg + 64 * pp + k];
                #pragma unroll
                for (int cc = 0; cc < 4; cc++) acc[cc][pp] += wr[cc] * iv;
            }
        }
    #pragma unroll
    for (int pp = 0; pp < 8; pp++) {
        int o = o0 + pg + 32 * pp;
        if (o < L2n)
            #pragma unroll
            for (int cc = 0; cc < 4; cc++) {
                float v = acc[cc][pp];
                g_h2[(size_t)(c0 + cc) * L2n + o] = v > 0.0f ? v : 0.2f * v;
            }
    }
}

// conv3: 64->128, fused leaky + channel partial sums. 512 threads, 256 pos, 128 oc, 2 ic-tiles.
__global__ void __launch_bounds__(512, 1) k_conv3(const float* __restrict__ w, const float* __restrict__ b) {
    extern __shared__ float sm[];
    float* sw = sm;              // [128][165]
    float* si = sm + 128 * 165;  // [32][520]
    int tid = threadIdx.x;
    int pg = tid & 31, c0 = (tid >> 5) * 8;
    int o0 = blockIdx.x * 256, j0 = 2 * o0 - 2;
    float acc[8][8];
    #pragma unroll
    for (int cc = 0; cc < 8; cc++) { float bb = b[c0 + cc];
        #pragma unroll
        for (int pp = 0; pp < 8; pp++) acc[cc][pp] = bb; }
    for (int tau = 0; tau < 2; tau++) {
        __syncthreads();
        for (int i = tid; i < 128 * 160; i += 512) {
            int oc = i / 160, r = i - oc * 160;
            sw[oc * 165 + r] = w[(size_t)oc * 320 + tau * 160 + r];
        }
        for (int ii = tid; ii < 32 * 516; ii += 512) {
            int ic = ii / 516, jj = ii - ic * 516, j = j0 + jj;
            si[ic * 520 + jj] = (j >= 0 && j < L2n) ? g_h2[(size_t)(tau * 32 + ic) * L2n + j] : 0.0f;
        }
        __syncthreads();
        for (int ic = 0; ic < 32; ic++)
            #pragma unroll
            for (int k = 0; k < 5; k++) {
                float wr[8];
                #pragma unroll
                for (int cc = 0; cc < 8; cc++) wr[cc] = sw[(c0 + cc) * 165 + ic * 5 + k];
                #pragma unroll
                for (int pp = 0; pp < 8; pp++) {
                    float iv = si[ic * 520 + 2 * pg + 64 * pp + k];
                    #pragma unroll
                    for (int cc = 0; cc < 8; cc++) acc[cc][pp] += wr[cc] * iv;
                }
            }
    }
    float cs[8];
    #pragma unroll
    for (int cc = 0; cc < 8; cc++) cs[cc] = 0.0f;
    #pragma unroll
    for (int pp = 0; pp < 8; pp++) {
        int o = o0 + pg + 32 * pp;
        if (o < L3n)
            #pragma unroll
            for (int cc = 0; cc < 8; cc++) {
                float v = acc[cc][pp];
                cs[cc] += (v > 0.0f ? v : 0.2f * v);
            }
    }
    #pragma unroll
    for (int off = 16; off > 0; off >>= 1)
        #pragma unroll
        for (int cc = 0; cc < 8; cc++)
            cs[cc] += __shfl_xor_sync(0xffffffffu, cs[cc], off);
    if (pg == 0)
        #pragma unroll
        for (int cc = 0; cc < 8; cc++)
            g_part3[(size_t)blockIdx.x * 128 + c0 + cc] = cs[cc];
}

__global__ void k_feat() {
    int c = blockIdx.x, tid = threadIdx.x;
    __shared__ double sd[256];
    double a = 0.0;
    for (int bi = tid; bi < NB3C; bi += 256) a += (double)g_part3[(size_t)bi * 128 + c];
    sd[tid] = a; __syncthreads();
    for (int s = 128; s > 0; s >>= 1) { if (tid < s) sd[tid] += sd[tid + s]; __syncthreads(); }
    if (tid == 0) g_feat[c] = (float)(sd[0] / (double)L3n);
}

__global__ void k_mlp(const float* __restrict__ w1, const float* __restrict__ b1,
                      const float* __restrict__ w2, const float* __restrict__ b2,
                      float* __restrict__ out) {
    __shared__ float sf[128], sred[256];
    int tid = threadIdx.x;
    if (tid < 128) sf[tid] = g_feat[tid];
    __syncthreads();
    float acc = b1[tid];
    for (int i = 0; i < 128; i++) acc += sf[i] * w1[i * 256 + tid];
    acc = acc > 0.0f ? acc : 0.2f * acc;
    sred[tid] = acc * w2[tid];
    __syncthreads();
    for (int s = 128; s > 0; s >>= 1) { if (tid < s) sred[tid] += sred[tid + s]; __syncthreads(); }
    if (tid == 0) out[0] = sred[0] + b2[0];
}

#define CONV2_SMEM ((64*165 + 32*520) * 4)
#define CONV3_SMEM ((128*165 + 32*520) * 4)

extern "C" void kernel_launch(void* const* d_in, const int* in_sizes, int n_in,
                              void* d_out, int out_size) {
    (void)in_sizes; (void)n_in; (void)out_size;
    const float* z   = (const float*)d_in[0];
    const float* bw  = (const float*)d_in[2];
    const float* fw  = (const float*)d_in[3];
    const float* hp  = (const float*)d_in[4];
    const float* tw1 = (const float*)d_in[5];  const float* tb1 = (const float*)d_in[6];
    const float* tw2 = (const float*)d_in[7];  const float* tb2 = (const float*)d_in[8];
    const float* tw3 = (const float*)d_in[9];  const float* tb3 = (const float*)d_in[10];
    const float* c1w = (const float*)d_in[11]; const float* c1b = (const float*)d_in[12];
    const float* c2w = (const float*)d_in[13]; const float* c2b = (const float*)d_in[14];
    const float* c3w = (const float*)d_in[15]; const float* c3b = (const float*)d_in[16];
    const float* mw1 = (const float*)d_in[17]; const float* mb1 = (const float*)d_in[18];
    const float* mw2 = (const float*)d_in[19]; const float* mb2 = (const float*)d_in[20];
    float* out = (float*)d_out;

    cudaFuncSetAttribute(k_conv2, cudaFuncAttributeMaxDynamicSharedMemorySize, CONV2_SMEM);
    cudaFuncSetAttribute(k_conv3, cudaFuncAttributeMaxDynamicSharedMemorySize, CONV3_SMEM);

    k_prep2<<<N2 / 256, 256>>>(z);
    int src = 1;
    for (int t = 0; t < 10; t++) {
        k_fft4<<<NQ2 / 256, 256>>>(src, 2 * t, -1.0f, 1.0f / (float)(N2 >> (2 * t)));
        src ^= 1;
    }
    k_fft2<<<1048576 / 256, 256>>>(src); src ^= 1;     // Z now in g_B
    k_prog<<<1024, 256>>>(tw1, tb1, tw2, tb2, tw3, tb3, hp);
    k_progfinal<<<1, 256>>>();
    k_wininit<<<1, 1>>>();
    k_passA<<<(Lt + 255) / 256, 256>>>(bw, fw);        // g_B -> g_A (X * mult)
    k_passB<<<N2 / 256, 256>>>();                      // g_A -> g_B (Z' for inverse)
    src = 0;
    for (int t = 0; t < 10; t++) {
        k_fft4<<<NQ2 / 256, 256>>>(src, 2 * t, +1.0f, 1.0f / (float)(N2 >> (2 * t)));
        src ^= 1;
    }
    k_fft2<<<1048576 / 256, 256>>>(src);               // time signal (packed) in g_A
    k_extract<<<(Lt + 255) / 256, 256>>>();
    k_conv1<<<(L1n + 255) / 256, 256>>>(c1w, c1b);
    k_conv2<<<(L2n + 255) / 256, 512, CONV2_SMEM>>>(c2w, c2b);
    k_conv3<<<(L3n + 255) / 256, 512, CONV3_SMEM>>>(c3w, c3b);
    k_feat<<<128, 256>>>();
    k_mlp<<<1, 256>>>(mw1, mb1, mw2, mb2, out);
}